// round 1
// baseline (speedup 1.0000x reference)
#include <cuda_runtime.h>
#include <math.h>

#define NA    4096
#define NB    8192
#define FDIM  133
#define BFDIM 147
#define HD    256
#define APM   64
#define NMOL  64
#define MAXNB 6

// ---------------- scratch (static device globals; no allocs allowed) ----------------
__device__ float g_qa[NA * FDIM];
__device__ float g_ka[NA * FDIM];
__device__ float g_va[NA * FDIM];
__device__ float g_fe[NA * FDIM];
__device__ float g_inputs[NB * HD];
__device__ float g_msg[NB * HD];
__device__ float g_amsg[NA * HD];
__device__ float g_tmp[NB * HD];     // dmpnn pre-activation / concat buffer (4096*389 fits)
__device__ float g_dmpnn[NB * HD];
__device__ float g_Q[NB * HD];
__device__ float g_K[NB * HD];
__device__ float g_V[NB * HD];
__device__ float g_attV[NB * HD];
__device__ float g_attm[NB * HD];
__device__ float g_atomh[NA * HD];
__device__ float g_hmwa[NA * HD];

// ---------------- generic fp32 GEMM: C[M,N] = A[M,K] @ B[K,N] (+bias)(+relu) -------
template <int RELU, int HASBIAS>
__global__ __launch_bounds__(256) void gemm_k(const float* __restrict__ A,
                                              const float* __restrict__ B,
                                              const float* __restrict__ bias,
                                              float* __restrict__ C,
                                              int Mm, int Nn, int Kk) {
    __shared__ float As[16 * 68];  // As[k][m], padded
    __shared__ float Bs[16 * 68];  // Bs[k][n], padded
    const int tid = threadIdx.x;
    const int tm = tid >> 4, tn = tid & 15;
    const int m0 = blockIdx.y * 64;
    const int n0 = blockIdx.x * 64;
    float acc[4][4] = {};
    for (int k0 = 0; k0 < Kk; k0 += 16) {
#pragma unroll
        for (int i = 0; i < 4; i++) {
            int idx = tid + i * 256;
            int row = idx >> 4, col = idx & 15;
            float vA = 0.f;
            if (m0 + row < Mm && k0 + col < Kk) vA = A[(size_t)(m0 + row) * Kk + k0 + col];
            As[col * 68 + row] = vA;
        }
#pragma unroll
        for (int i = 0; i < 4; i++) {
            int idx = tid + i * 256;
            int row = idx >> 6, col = idx & 63;
            float vB = 0.f;
            if (k0 + row < Kk && n0 + col < Nn) vB = B[(size_t)(k0 + row) * Nn + n0 + col];
            Bs[row * 68 + col] = vB;
        }
        __syncthreads();
#pragma unroll
        for (int kk = 0; kk < 16; kk++) {
            float4 a4 = *(const float4*)&As[kk * 68 + tm * 4];
            float4 b4 = *(const float4*)&Bs[kk * 68 + tn * 4];
            float av[4] = {a4.x, a4.y, a4.z, a4.w};
            float bv[4] = {b4.x, b4.y, b4.z, b4.w};
#pragma unroll
            for (int i = 0; i < 4; i++)
#pragma unroll
                for (int j = 0; j < 4; j++) acc[i][j] += av[i] * bv[j];
        }
        __syncthreads();
    }
#pragma unroll
    for (int i = 0; i < 4; i++) {
        int m = m0 + tm * 4 + i;
        if (m >= Mm) continue;
#pragma unroll
        for (int j = 0; j < 4; j++) {
            int n = n0 + tn * 4 + j;
            if (n >= Nn) continue;
            float v = acc[i][j];
            if (HASBIAS) v += bias[n];
            if (RELU) v = fmaxf(v, 0.f);
            C[(size_t)m * Nn + n] = v;
        }
    }
}

// ---------------- flash attention over bonds: attV = softmax(QK^T/16) @ V ----------
#define FL_SMEM_FLOATS (256 * 68 * 2 + 64 * 256 + 64 * 64 + 192)
__global__ __launch_bounds__(256, 1) void flash_k() {
    extern __shared__ float sm[];
    float* QsT = sm;                 // [256][68] (k-major, padded)
    float* KsT = QsT + 256 * 68;     // [256][68]
    float* Vs = KsT + 256 * 68;      // [64][256]
    float* Sb = Vs + 64 * 256;       // [64][64]
    float* mrow = Sb + 64 * 64;      // 64
    float* lrow = mrow + 64;         // 64
    float* fsc = lrow + 64;          // 64
    const int tid = threadIdx.x;
    const int row0 = blockIdx.x * 64;

    for (int idx = tid; idx < 64 * 256; idx += 256) {
        int a = idx >> 8, k = idx & 255;
        QsT[k * 68 + a] = g_Q[(size_t)(row0 + a) * HD + k];
    }
    if (tid < 64) { mrow[tid] = -1e30f; lrow[tid] = 0.f; }

    const int pr = tid >> 3;
    const int cg = tid & 7;
    const int r0 = pr * 2, r1 = r0 + 1;
    float acc0[32], acc1[32];
#pragma unroll
    for (int c = 0; c < 32; c++) { acc0[c] = 0.f; acc1[c] = 0.f; }
    const int ty = tid >> 4, tx = tid & 15;
    __syncthreads();

    for (int kb = 0; kb < NB; kb += 64) {
        for (int idx = tid; idx < 64 * 256; idx += 256) {
            int b = idx >> 8, k = idx & 255;
            KsT[k * 68 + b] = g_K[(size_t)(kb + b) * HD + k];
        }
        for (int idx = tid * 4; idx < 64 * 256; idx += 1024) {
            *(float4*)&Vs[idx] = *(const float4*)&g_V[(size_t)kb * HD + idx];
        }
        __syncthreads();
        // S = Q K^T * (1/16)
        {
            float sa[4][4] = {};
#pragma unroll 4
            for (int k = 0; k < 256; k++) {
                float4 qa = *(const float4*)&QsT[k * 68 + ty * 4];
                float4 kv = *(const float4*)&KsT[k * 68 + tx * 4];
                float av[4] = {qa.x, qa.y, qa.z, qa.w};
                float bv[4] = {kv.x, kv.y, kv.z, kv.w};
#pragma unroll
                for (int i = 0; i < 4; i++)
#pragma unroll
                    for (int j = 0; j < 4; j++) sa[i][j] += av[i] * bv[j];
            }
#pragma unroll
            for (int i = 0; i < 4; i++)
#pragma unroll
                for (int j = 0; j < 4; j++)
                    Sb[(ty * 4 + i) * 64 + tx * 4 + j] = sa[i][j] * 0.0625f;
        }
        __syncthreads();
        if (tid < 64) {
            float mc = -1e30f;
#pragma unroll 8
            for (int j = 0; j < 64; j++) mc = fmaxf(mc, Sb[tid * 64 + j]);
            float mn = fmaxf(mrow[tid], mc);
            fsc[tid] = __expf(mrow[tid] - mn);
            mrow[tid] = mn;
        }
        __syncthreads();
#pragma unroll
        for (int i = 0; i < 4; i++) {
            float mi = mrow[ty * 4 + i];
#pragma unroll
            for (int j = 0; j < 4; j++) {
                int off = (ty * 4 + i) * 64 + tx * 4 + j;
                Sb[off] = __expf(Sb[off] - mi);
            }
        }
        __syncthreads();
        if (tid < 64) {
            float s = 0.f;
#pragma unroll 8
            for (int j = 0; j < 64; j++) s += Sb[tid * 64 + j];
            lrow[tid] = lrow[tid] * fsc[tid] + s;
        }
        // O rescale + accumulate P@V
        {
            float f0 = fsc[r0], f1 = fsc[r1];
#pragma unroll
            for (int c = 0; c < 32; c++) { acc0[c] *= f0; acc1[c] *= f1; }
#pragma unroll 2
            for (int j = 0; j < 64; j++) {
                float p0 = Sb[r0 * 64 + j], p1 = Sb[r1 * 64 + j];
#pragma unroll
                for (int i = 0; i < 8; i++) {
                    float4 v = *(const float4*)&Vs[j * 256 + cg * 32 + i * 4];
                    acc0[i * 4 + 0] += p0 * v.x; acc0[i * 4 + 1] += p0 * v.y;
                    acc0[i * 4 + 2] += p0 * v.z; acc0[i * 4 + 3] += p0 * v.w;
                    acc1[i * 4 + 0] += p1 * v.x; acc1[i * 4 + 1] += p1 * v.y;
                    acc1[i * 4 + 2] += p1 * v.z; acc1[i * 4 + 3] += p1 * v.w;
                }
            }
        }
        __syncthreads();
    }
    float li0 = 1.f / lrow[r0], li1 = 1.f / lrow[r1];
#pragma unroll
    for (int c = 0; c < 32; c++) {
        g_attV[(size_t)(row0 + r0) * HD + cg * 32 + c] = acc0[c] * li0;
        g_attV[(size_t)(row0 + r1) * HD + cg * 32 + c] = acc1[c] * li1;
    }
}

// ---------------- per-molecule atom self-attention + residual + LayerNorm ----------
#define AT_SMEM_FLOATS (4 * 64 * 136 + 64 * 64 + 512 + 128)
__global__ __launch_bounds__(256, 1) void atom_attn_ln_k(const float* __restrict__ xg,
                                                         const float* __restrict__ gw,
                                                         const float* __restrict__ bw) {
    extern __shared__ float sm[];
    float* sx = sm;                 // [64][136]
    float* sq = sx + 64 * 136;
    float* sk = sq + 64 * 136;
    float* sv = sk + 64 * 136;
    float* ss = sv + 64 * 136;      // [64][64]
    float* sred = ss + 4096;        // 512
    float* srow = sred + 512;       // 128 (mu, rstd)
    const int tid = threadIdx.x;
    const int base = blockIdx.x * 64;

    for (int idx = tid; idx < 64 * FDIM; idx += 256) {
        int a = idx / FDIM, f = idx - a * FDIM;
        size_t go = (size_t)(base + a) * FDIM + f;
        sx[a * 136 + f] = xg[go];
        sq[a * 136 + f] = g_qa[go];
        sk[a * 136 + f] = g_ka[go];
        sv[a * 136 + f] = g_va[go];
    }
    __syncthreads();
    {
        int ty = tid >> 4, tx = tid & 15;
        float acc[4][4] = {};
        for (int h = 0; h < FDIM; h++) {
            float qv[4], kv[4];
#pragma unroll
            for (int i = 0; i < 4; i++) {
                qv[i] = sq[(ty * 4 + i) * 136 + h];
                kv[i] = sk[(tx * 4 + i) * 136 + h];
            }
#pragma unroll
            for (int i = 0; i < 4; i++)
#pragma unroll
                for (int j = 0; j < 4; j++) acc[i][j] += qv[i] * kv[j];
        }
        float scl = rsqrtf(133.0f);
#pragma unroll
        for (int i = 0; i < 4; i++)
#pragma unroll
            for (int j = 0; j < 4; j++)
                ss[(ty * 4 + i) * 64 + tx * 4 + j] = acc[i][j] * scl;
    }
    __syncthreads();
    if (tid < 64) {
        float mx = -1e30f;
        for (int j = 0; j < 64; j++) mx = fmaxf(mx, ss[tid * 64 + j]);
        float s = 0.f;
        for (int j = 0; j < 64; j++) {
            float e = __expf(ss[tid * 64 + j] - mx);
            ss[tid * 64 + j] = e; s += e;
        }
        float inv = 1.f / s;
        for (int j = 0; j < 64; j++) ss[tid * 64 + j] *= inv;
    }
    __syncthreads();
    const int r = tid >> 2, qd = tid & 3;
    const int f0 = qd * 34;
    float tv[34];
#pragma unroll
    for (int f = 0; f < 34; f++) tv[f] = 0.f;
    for (int b = 0; b < 64; b++) {
        float p = ss[r * 64 + b];
        const float* vb = &sv[b * 136 + f0];
#pragma unroll
        for (int f = 0; f < 34; f++)
            if (f0 + f < FDIM) tv[f] += p * vb[f];
    }
    float s1 = 0.f;
#pragma unroll
    for (int f = 0; f < 34; f++)
        if (f0 + f < FDIM) { tv[f] += sx[r * 136 + f0 + f]; s1 += tv[f]; }
    sred[tid] = s1;
    __syncthreads();
    if (qd == 0) {
        float mu = (sred[tid] + sred[tid + 1] + sred[tid + 2] + sred[tid + 3]) * (1.f / 133.f);
        srow[r] = mu;
    }
    __syncthreads();
    float mu = srow[r];
    float s2 = 0.f;
#pragma unroll
    for (int f = 0; f < 34; f++)
        if (f0 + f < FDIM) { float d = tv[f] - mu; s2 += d * d; }
    sred[tid] = s2;
    __syncthreads();
    if (qd == 0) {
        float var = (sred[tid] + sred[tid + 1] + sred[tid + 2] + sred[tid + 3]) * (1.f / 133.f);
        srow[64 + r] = rsqrtf(var + 1e-5f);
    }
    __syncthreads();
    float rstd = srow[64 + r];
#pragma unroll
    for (int f = 0; f < 34; f++) {
        int fg = f0 + f;
        if (fg < FDIM)
            g_fe[(size_t)(base + r) * FDIM + fg] = (tv[f] - mu) * rstd * gw[fg] + bw[fg];
    }
}

// ---------------- elementwise / gather kernels --------------------------------------
__global__ void relu_copy_k(const float* __restrict__ in, float* __restrict__ out, int n) {
    int i = blockIdx.x * blockDim.x + threadIdx.x;
    if (i < n) out[i] = fmaxf(in[i], 0.f);
}

__global__ void gather_sum_k(const int* __restrict__ a2b) {
    __shared__ int idx[MAXNB];
    int a = blockIdx.x, t = threadIdx.x;
    if (t < MAXNB) idx[t] = a2b[a * MAXNB + t];
    __syncthreads();
    float s = 0.f;
#pragma unroll
    for (int j = 0; j < MAXNB; j++) s += g_msg[(size_t)idx[j] * HD + t];
    g_amsg[(size_t)a * HD + t] = s;
}

__global__ void dmpnn_pre_k(const int* __restrict__ b2a, const int* __restrict__ b2revb) {
    int b = blockIdx.x, t = threadIdx.x;
    int ia = __ldg(&b2a[b]), ir = __ldg(&b2revb[b]);
    g_tmp[(size_t)b * HD + t] = g_amsg[(size_t)ia * HD + t] - g_msg[(size_t)ir * HD + t];
}

__global__ void combine_k(const float* __restrict__ wal, const float* __restrict__ walb) {
    __shared__ float red[256];
    __shared__ float salpha;
    int b = blockIdx.x, t = threadIdx.x;
    size_t o = (size_t)b * HD + t;
    float d = g_dmpnn[o], am = g_attm[o];
    red[t] = d * wal[t] + am * wal[256 + t];
    __syncthreads();
    for (int s = 128; s > 0; s >>= 1) {
        if (t < s) red[t] += red[t + s];
        __syncthreads();
    }
    if (t == 0) salpha = 1.f / (1.f + __expf(-(red[0] + walb[0])));
    __syncthreads();
    float al = salpha;
    g_msg[o] = fmaxf(g_inputs[o] + al * d + (1.f - al) * am, 0.f);
}

__global__ void concat_k() {
    int i = blockIdx.x * blockDim.x + threadIdx.x;
    if (i >= NA * (FDIM + HD)) return;
    int row = i / (FDIM + HD), c = i - row * (FDIM + HD);
    g_tmp[i] = (c < FDIM) ? g_fe[(size_t)row * FDIM + c]
                          : g_amsg[(size_t)row * HD + (c - FDIM)];
}

// ---------------- per-molecule attentive pooling -------------------------------------
#define MP_SMEM_FLOATS (2 * 64 * 260 + 4096)
__global__ __launch_bounds__(256, 1) void mol_pool_k(const float* __restrict__ Wb,
                                                     const float* __restrict__ bb,
                                                     float* __restrict__ outg) {
    extern __shared__ float sm[];
    float* shm = sm;                 // [64][260]  (atom_h)
    float* sw = shm + 64 * 260;      // [64][260]  (hm@Wa, later t=aw@hm)
    float* ssc = sw + 64 * 260;      // [64][64]
    const int tid = threadIdx.x;
    const int base = blockIdx.x * 64;
    for (int idx = tid; idx < 64 * HD; idx += 256) {
        int a = idx >> 8, c = idx & 255;
        shm[a * 260 + c] = g_atomh[(size_t)(base + a) * HD + c];
        sw[a * 260 + c] = g_hmwa[(size_t)(base + a) * HD + c];
    }
    __syncthreads();
    {
        int ty = tid >> 4, tx = tid & 15;
        float acc[4][4] = {};
        for (int h = 0; h < HD; h++) {
            float qv[4], kv[4];
#pragma unroll
            for (int i = 0; i < 4; i++) {
                qv[i] = sw[(ty * 4 + i) * 260 + h];
                kv[i] = shm[(tx * 4 + i) * 260 + h];
            }
#pragma unroll
            for (int i = 0; i < 4; i++)
#pragma unroll
                for (int j = 0; j < 4; j++) acc[i][j] += qv[i] * kv[j];
        }
#pragma unroll
        for (int i = 0; i < 4; i++)
#pragma unroll
            for (int j = 0; j < 4; j++)
                ssc[(ty * 4 + i) * 64 + tx * 4 + j] = acc[i][j];
    }
    __syncthreads();
    if (tid < 64) {
        float mx = -1e30f;
        for (int j = 0; j < 64; j++) mx = fmaxf(mx, ssc[tid * 64 + j]);
        float s = 0.f;
        for (int j = 0; j < 64; j++) {
            float e = __expf(ssc[tid * 64 + j] - mx);
            ssc[tid * 64 + j] = e; s += e;
        }
        float inv = 1.f / s;
        for (int j = 0; j < 64; j++) ssc[tid * 64 + j] *= inv;
    }
    __syncthreads();
    const int c = tid;
    float acc[64];
#pragma unroll
    for (int a = 0; a < 64; a++) acc[a] = 0.f;
    for (int b = 0; b < 64; b++) {
        float hv = shm[b * 260 + c];
#pragma unroll 16
        for (int a = 0; a < 64; a++) acc[a] += ssc[a * 64 + b] * hv;
    }
    __syncthreads();
    for (int a = 0; a < 64; a++) sw[a * 260 + c] = acc[a];
    __syncthreads();
#pragma unroll
    for (int a = 0; a < 64; a++) acc[a] = 0.f;
    for (int k = 0; k < HD; k++) {
        float wv = Wb[(size_t)k * HD + c];
#pragma unroll 16
        for (int a = 0; a < 64; a++) acc[a] += sw[a * 260 + k] * wv;
    }
    float bv = bb[c];
    float s = 0.f;
    for (int a = 0; a < 64; a++) {
        float t = fmaxf(acc[a] + bv, 0.f);
        s += shm[a * 260 + c] + t;
    }
    outg[(size_t)blockIdx.x * HD + c] = s * (1.f / 64.f);
}

// ---------------- host driver --------------------------------------------------------
static float* symf(const void* s) {
    void* p = nullptr;
    cudaGetSymbolAddress(&p, s);
    return (float*)p;
}

extern "C" void kernel_launch(void* const* d_in, const int* in_sizes, int n_in,
                              void* d_out, int out_size) {
    const float* f_atoms = (const float*)d_in[0];
    const float* f_bonds = (const float*)d_in[1];
    const float* Wq_atom = (const float*)d_in[2];
    const float* Wk_atom = (const float*)d_in[3];
    const float* Wv_atom = (const float*)d_in[4];
    const float* ln_g = (const float*)d_in[5];
    const float* ln_b = (const float*)d_in[6];
    const float* Wi = (const float*)d_in[7];
    const float* Wh = (const float*)d_in[8];
    const float* Wq = (const float*)d_in[9];
    const float* Wk = (const float*)d_in[10];
    const float* Wv = (const float*)d_in[11];
    const float* Wa = (const float*)d_in[12];
    const float* Walw = (const float*)d_in[13];
    const float* Walb = (const float*)d_in[14];
    const float* Wow = (const float*)d_in[15];
    const float* Wob = (const float*)d_in[16];
    const float* Wbw = (const float*)d_in[17];
    const float* Wbb = (const float*)d_in[18];
    const int* a2b = (const int*)d_in[19];
    const int* b2a = (const int*)d_in[20];
    const int* b2revb = (const int*)d_in[21];
    float* out = (float*)d_out;

    float* p_qa = symf(g_qa);
    float* p_ka = symf(g_ka);
    float* p_va = symf(g_va);
    float* p_inputs = symf(g_inputs);
    float* p_msg = symf(g_msg);
    float* p_tmp = symf(g_tmp);
    float* p_dmpnn = symf(g_dmpnn);
    float* p_Q = symf(g_Q);
    float* p_K = symf(g_K);
    float* p_V = symf(g_V);
    float* p_attV = symf(g_attV);
    float* p_attm = symf(g_attm);
    float* p_atomh = symf(g_atomh);
    float* p_hmwa = symf(g_hmwa);

    const int FL_SMEM = FL_SMEM_FLOATS * 4;
    const int AT_SMEM = AT_SMEM_FLOATS * 4;
    const int MP_SMEM = MP_SMEM_FLOATS * 4;
    cudaFuncSetAttribute(flash_k, cudaFuncAttributeMaxDynamicSharedMemorySize, FL_SMEM);
    cudaFuncSetAttribute(atom_attn_ln_k, cudaFuncAttributeMaxDynamicSharedMemorySize, AT_SMEM);
    cudaFuncSetAttribute(mol_pool_k, cudaFuncAttributeMaxDynamicSharedMemorySize, MP_SMEM);

    // --- atom enhancement ---
    dim3 gqa((FDIM + 63) / 64, (NA + 63) / 64);
    gemm_k<0, 0><<<gqa, 256>>>(f_atoms, Wq_atom, nullptr, p_qa, NA, FDIM, FDIM);
    gemm_k<0, 0><<<gqa, 256>>>(f_atoms, Wk_atom, nullptr, p_ka, NA, FDIM, FDIM);
    gemm_k<0, 0><<<gqa, 256>>>(f_atoms, Wv_atom, nullptr, p_va, NA, FDIM, FDIM);
    atom_attn_ln_k<<<NMOL, 256, AT_SMEM>>>(f_atoms, ln_g, ln_b);

    // --- bond message init ---
    dim3 gb(HD / 64, NB / 64);
    gemm_k<0, 0><<<gb, 256>>>(f_bonds, Wi, nullptr, p_inputs, NB, HD, BFDIM);
    relu_copy_k<<<(NB * HD + 255) / 256, 256>>>(p_inputs, p_msg, NB * HD);

    // --- depth loop (DEPTH-1 = 3 iterations) ---
    for (int it = 0; it < 3; it++) {
        gather_sum_k<<<NA, 256>>>(a2b);
        dmpnn_pre_k<<<NB, 256>>>(b2a, b2revb);
        gemm_k<0, 0><<<gb, 256>>>(p_tmp, Wh, nullptr, p_dmpnn, NB, HD, HD);
        gemm_k<0, 0><<<gb, 256>>>(p_msg, Wq, nullptr, p_Q, NB, HD, HD);
        gemm_k<0, 0><<<gb, 256>>>(p_msg, Wk, nullptr, p_K, NB, HD, HD);
        gemm_k<0, 0><<<gb, 256>>>(p_msg, Wv, nullptr, p_V, NB, HD, HD);
        flash_k<<<NB / 64, 256, FL_SMEM>>>();
        gemm_k<0, 0><<<gb, 256>>>(p_attV, Wa, nullptr, p_attm, NB, HD, HD);
        combine_k<<<NB, 256>>>(Walw, Walb);
    }

    // --- readout ---
    gather_sum_k<<<NA, 256>>>(a2b);
    concat_k<<<(NA * (FDIM + HD) + 255) / 256, 256>>>();
    dim3 ga(HD / 64, NA / 64);
    gemm_k<1, 1><<<ga, 256>>>(p_tmp, Wow, Wob, p_atomh, NA, HD, FDIM + HD);

    // --- pooling ---
    gemm_k<0, 0><<<ga, 256>>>(p_atomh, Wa, nullptr, p_hmwa, NA, HD, HD);
    mol_pool_k<<<NMOL, 256, MP_SMEM>>>(Wbw, Wbb, out);
}